// round 2
// baseline (speedup 1.0000x reference)
#include <cuda_runtime.h>
#include <cstdint>

// speed[n,d] = sum_{f,m} Cont[f] * exp(-||P[n]-S[f,m]||^2) * V[f,m,d]
// Rewrite: exp(-||x-y||^2) = exp2(-L*x^2) * exp2( x.(2L*y) - L*y^2 ), L = log2(e)
// Per-point factor exp2(-L*x^2) hoisted out of the m-loop.
// Support data pre-scaled & pair-interleaved in shared so adjacent m values are
// processed with packed fma.rn.f32x2. Main loop steps 2 pairs (4 m) so the
// vc2 components of both pairs come from a single LDS.128 (3.5 LDS/pair).

#define FMA2(d, a, b, c) \
    asm("fma.rn.f32x2 %0, %1, %2, %3;" : "=l"(d) : "l"(a), "l"(b), "l"(c))

__device__ __forceinline__ uint64_t splat2(float x) {
    uint64_t r;
    asm("mov.b64 %0, {%1, %1};" : "=l"(r) : "f"(x));
    return r;
}
__device__ __forceinline__ void unpack2(float& lo, float& hi, uint64_t v) {
    asm("mov.b64 {%0, %1}, %2;" : "=f"(lo), "=f"(hi) : "l"(v));
}
__device__ __forceinline__ uint64_t pack2(float lo, float hi) {
    uint64_t r;
    asm("mov.b64 %0, {%1, %2};" : "=l"(r) : "f"(lo), "f"(hi));
    return r;
}
__device__ __forceinline__ float ex2f_(float x) {
    float r;
    asm("ex2.approx.f32 %0, %1;" : "=f"(r) : "f"(x));
    return r;
}

static constexpr int BLOCK = 448;   // 14 warps; smem forces 1 CTA/SM -> 147 CTAs = 1 wave

__global__ __launch_bounds__(BLOCK, 1)
void rbf_speed_kernel(const float* __restrict__ Points,
                      const float* __restrict__ supp_pts,
                      const float* __restrict__ supp_vec,
                      const float* __restrict__ Cont,
                      float* __restrict__ out,
                      int N, int M, int FM)
{
    extern __shared__ __align__(16) float smem[];
    const float L2E = 1.4426950408889634f;

    // Shared layout (per m-pair p; even m in lane-lo, odd m in lane-hi):
    //  A [0..8P)      : per pair two quads {ys0,ys0, ys1,ys1} {ys2,ys2, c,c}
    //  B [8P..12P)    : per pair one quad  {vc0,vc0, vc1,vc1}
    //  C [12P..14P)   : vc2 pairs, contiguous (quad covers two pairs)
    const int P    = FM >> 1;
    const int offB = 8 * P;
    const int offC = 12 * P;

    for (int m = threadIdx.x; m < FM; m += BLOCK) {
        int p = m >> 1, h = m & 1;
        float y0 = supp_pts[3 * m + 0];
        float y1 = supp_pts[3 * m + 1];
        float y2 = supp_pts[3 * m + 2];
        float v0 = supp_vec[3 * m + 0];
        float v1 = supp_vec[3 * m + 1];
        float v2 = supp_vec[3 * m + 2];
        float cont = Cont[m / M];
        float c = -L2E * (y0 * y0 + y1 * y1 + y2 * y2);
        smem[8 * p + 0 + h] = 2.0f * L2E * y0;
        smem[8 * p + 2 + h] = 2.0f * L2E * y1;
        smem[8 * p + 4 + h] = 2.0f * L2E * y2;
        smem[8 * p + 6 + h] = c;
        smem[offB + 4 * p + 0 + h] = cont * v0;
        smem[offB + 4 * p + 2 + h] = cont * v1;
        smem[offC + 2 * p + h]     = cont * v2;
    }
    __syncthreads();

    int i = blockIdx.x * BLOCK + threadIdx.x;
    if (i >= N) return;

    float x0 = Points[3 * i + 0];
    float x1 = Points[3 * i + 1];
    float x2 = Points[3 * i + 2];
    uint64_t X0 = splat2(x0), X1 = splat2(x1), X2 = splat2(x2);
    float scale = ex2f_(-L2E * (x0 * x0 + x1 * x1 + x2 * x2));

    const ulonglong2* __restrict__ Ap = (const ulonglong2*)smem;          // 2 quads/pair
    const ulonglong2* __restrict__ Bp = (const ulonglong2*)(smem + offB); // 1 quad/pair
    const ulonglong2* __restrict__ Cq = (const ulonglong2*)(smem + offC); // 1 quad/2 pairs

    uint64_t acc0 = 0ull, acc1 = 0ull, acc2 = 0ull;  // packed {0.f,0.f}

    #pragma unroll 2
    for (int p = 0; p < P; p += 2) {
        // pair p
        ulonglong2 a0 = Ap[2 * p];         // ys0 | ys1
        ulonglong2 b0 = Ap[2 * p + 1];     // ys2 | c
        // pair p+1
        ulonglong2 a1 = Ap[2 * p + 2];
        ulonglong2 b1 = Ap[2 * p + 3];
        ulonglong2 v0 = Bp[p];             // vc0 | vc1 (pair p)
        ulonglong2 v1 = Bp[p + 1];         // vc0 | vc1 (pair p+1)
        ulonglong2 c2 = Cq[p >> 1];        // vc2 pair p | vc2 pair p+1

        uint64_t t0, t1;
        FMA2(t0, X0, a0.x, b0.y);
        FMA2(t0, X1, a0.y, t0);
        FMA2(t0, X2, b0.x, t0);
        FMA2(t1, X0, a1.x, b1.y);
        FMA2(t1, X1, a1.y, t1);
        FMA2(t1, X2, b1.x, t1);

        float tl, th;
        unpack2(tl, th, t0);
        uint64_t k0 = pack2(ex2f_(tl), ex2f_(th));
        unpack2(tl, th, t1);
        uint64_t k1 = pack2(ex2f_(tl), ex2f_(th));

        FMA2(acc0, k0, v0.x, acc0);
        FMA2(acc1, k0, v0.y, acc1);
        FMA2(acc2, k0, c2.x, acc2);
        FMA2(acc0, k1, v1.x, acc0);
        FMA2(acc1, k1, v1.y, acc1);
        FMA2(acc2, k1, c2.y, acc2);
    }

    float a0l, a0h, a1l, a1h, a2l, a2h;
    unpack2(a0l, a0h, acc0);
    unpack2(a1l, a1h, acc1);
    unpack2(a2l, a2h, acc2);
    out[3 * i + 0] = scale * (a0l + a0h);
    out[3 * i + 1] = scale * (a1l + a1h);
    out[3 * i + 2] = scale * (a2l + a2h);
}

extern "C" void kernel_launch(void* const* d_in, const int* in_sizes, int n_in,
                              void* d_out, int out_size)
{
    const float* Points   = (const float*)d_in[0];
    const float* supp_pts = (const float*)d_in[1];
    const float* supp_vec = (const float*)d_in[2];
    const float* Cont     = (const float*)d_in[3];
    float* out = (float*)d_out;

    int N  = in_sizes[0] / 3;       // 65536
    int F  = in_sizes[3];           // 8
    int FM = in_sizes[1] / 3;       // 4096
    int M  = FM / F;                // 512

    size_t smem_bytes = (size_t)FM * 28;  // 7 floats per support point = 114688 B
    cudaFuncSetAttribute(rbf_speed_kernel,
                         cudaFuncAttributeMaxDynamicSharedMemorySize,
                         (int)smem_bytes);

    int grid = (N + BLOCK - 1) / BLOCK;   // 147 CTAs
    rbf_speed_kernel<<<grid, BLOCK, smem_bytes>>>(
        Points, supp_pts, supp_vec, Cont, out, N, M, FM);
}

// round 9
// speedup vs baseline: 1.1148x; 1.1148x over previous
#include <cuda_runtime.h>
#include <cstdint>

// speed[n,d] = sum_{f,m} Cont[f] * exp(-||P[n]-S[f,m]||^2) * V[f,m,d]
// exp(-||x-y||^2) = exp2(-L*x^2) * exp2( x.(2L*y) - L*y^2 ), L = log2(e)
// Support data pre-scaled & pair-interleaved in shared; packed fma.rn.f32x2.
// Each thread processes TWO points so every shared load is amortized 2x
// (R2 ncu showed L1/shared at 77% = binding; MUFU floor is ~115K cyc/SM).

#define FMA2(d, a, b, c) \
    asm("fma.rn.f32x2 %0, %1, %2, %3;" : "=l"(d) : "l"(a), "l"(b), "l"(c))

__device__ __forceinline__ uint64_t splat2(float x) {
    uint64_t r;
    asm("mov.b64 %0, {%1, %1};" : "=l"(r) : "f"(x));
    return r;
}
__device__ __forceinline__ void unpack2(float& lo, float& hi, uint64_t v) {
    asm("mov.b64 {%0, %1}, %2;" : "=f"(lo), "=f"(hi) : "l"(v));
}
__device__ __forceinline__ uint64_t pack2(float lo, float hi) {
    uint64_t r;
    asm("mov.b64 %0, {%1, %2};" : "=l"(r) : "f"(lo), "f"(hi));
    return r;
}
__device__ __forceinline__ float ex2f_(float x) {
    float r;
    asm("ex2.approx.f32 %0, %1;" : "=f"(r) : "f"(x));
    return r;
}

static constexpr int BLOCK = 224;   // 7 warps; 2 points/thread -> 448 pts/CTA -> 147 CTAs = 1 wave

__global__ __launch_bounds__(BLOCK, 1)
void rbf_speed_kernel(const float* __restrict__ Points,
                      const float* __restrict__ supp_pts,
                      const float* __restrict__ supp_vec,
                      const float* __restrict__ Cont,
                      float* __restrict__ out,
                      int N, int M, int FM)
{
    extern __shared__ __align__(16) float smem[];
    const float L2E = 1.4426950408889634f;

    // Shared layout (per m-pair p; even m lane-lo, odd m lane-hi):
    //  A [0..8P)    : per pair two quads {ys0,ys0, ys1,ys1} {ys2,ys2, c,c}
    //  B [8P..12P)  : per pair one quad  {vc0,vc0, vc1,vc1}
    //  C [12P..14P) : vc2 pairs contiguous (one quad covers two pairs)
    const int P    = FM >> 1;
    const int offB = 8 * P;
    const int offC = 12 * P;

    for (int m = threadIdx.x; m < FM; m += BLOCK) {
        int p = m >> 1, h = m & 1;
        float y0 = supp_pts[3 * m + 0];
        float y1 = supp_pts[3 * m + 1];
        float y2 = supp_pts[3 * m + 2];
        float v0 = supp_vec[3 * m + 0];
        float v1 = supp_vec[3 * m + 1];
        float v2 = supp_vec[3 * m + 2];
        float cont = Cont[m / M];
        float c = -L2E * (y0 * y0 + y1 * y1 + y2 * y2);
        smem[8 * p + 0 + h] = 2.0f * L2E * y0;
        smem[8 * p + 2 + h] = 2.0f * L2E * y1;
        smem[8 * p + 4 + h] = 2.0f * L2E * y2;
        smem[8 * p + 6 + h] = c;
        smem[offB + 4 * p + 0 + h] = cont * v0;
        smem[offB + 4 * p + 2 + h] = cont * v1;
        smem[offC + 2 * p + h]     = cont * v2;
    }
    __syncthreads();

    // Two points per thread, one CTA covers 2*BLOCK consecutive points.
    int base = blockIdx.x * (2 * BLOCK) + threadIdx.x;
    int iA = base;              // first point
    int iB = base + BLOCK;      // second point
    bool wA = iA < N, wB = iB < N;
    if (!wA) return;            // iA < iB, so !wA implies !wB
    int jB = wB ? iB : iA;      // clamp: harmless duplicate work if B invalid

    float xa0 = Points[3 * iA + 0], xa1 = Points[3 * iA + 1], xa2 = Points[3 * iA + 2];
    float xb0 = Points[3 * jB + 0], xb1 = Points[3 * jB + 1], xb2 = Points[3 * jB + 2];
    uint64_t XA0 = splat2(xa0), XA1 = splat2(xa1), XA2 = splat2(xa2);
    uint64_t XB0 = splat2(xb0), XB1 = splat2(xb1), XB2 = splat2(xb2);
    float scaleA = ex2f_(-L2E * (xa0 * xa0 + xa1 * xa1 + xa2 * xa2));
    float scaleB = ex2f_(-L2E * (xb0 * xb0 + xb1 * xb1 + xb2 * xb2));

    const ulonglong2* __restrict__ Ap = (const ulonglong2*)smem;
    const ulonglong2* __restrict__ Bp = (const ulonglong2*)(smem + offB);
    const ulonglong2* __restrict__ Cq = (const ulonglong2*)(smem + offC);

    uint64_t accA0 = 0ull, accA1 = 0ull, accA2 = 0ull;
    uint64_t accB0 = 0ull, accB1 = 0ull, accB2 = 0ull;

    #pragma unroll 2
    for (int p = 0; p < P; p += 2) {
        ulonglong2 a0 = Ap[2 * p];        // ys0 | ys1  (pair p)
        ulonglong2 b0 = Ap[2 * p + 1];    // ys2 | c
        ulonglong2 a1 = Ap[2 * p + 2];    // (pair p+1)
        ulonglong2 b1 = Ap[2 * p + 3];
        ulonglong2 v0 = Bp[p];            // vc0 | vc1  (pair p)
        ulonglong2 v1 = Bp[p + 1];        //            (pair p+1)
        ulonglong2 c2 = Cq[p >> 1];       // vc2 p | vc2 p+1

        uint64_t tA0, tA1, tB0, tB1;
        FMA2(tA0, XA0, a0.x, b0.y);
        FMA2(tB0, XB0, a0.x, b0.y);
        FMA2(tA1, XA0, a1.x, b1.y);
        FMA2(tB1, XB0, a1.x, b1.y);
        FMA2(tA0, XA1, a0.y, tA0);
        FMA2(tB0, XB1, a0.y, tB0);
        FMA2(tA1, XA1, a1.y, tA1);
        FMA2(tB1, XB1, a1.y, tB1);
        FMA2(tA0, XA2, b0.x, tA0);
        FMA2(tB0, XB2, b0.x, tB0);
        FMA2(tA1, XA2, b1.x, tA1);
        FMA2(tB1, XB2, b1.x, tB1);

        float lo, hi;
        unpack2(lo, hi, tA0); uint64_t kA0 = pack2(ex2f_(lo), ex2f_(hi));
        unpack2(lo, hi, tB0); uint64_t kB0 = pack2(ex2f_(lo), ex2f_(hi));
        unpack2(lo, hi, tA1); uint64_t kA1 = pack2(ex2f_(lo), ex2f_(hi));
        unpack2(lo, hi, tB1); uint64_t kB1 = pack2(ex2f_(lo), ex2f_(hi));

        FMA2(accA0, kA0, v0.x, accA0);
        FMA2(accA1, kA0, v0.y, accA1);
        FMA2(accA2, kA0, c2.x, accA2);
        FMA2(accB0, kB0, v0.x, accB0);
        FMA2(accB1, kB0, v0.y, accB1);
        FMA2(accB2, kB0, c2.x, accB2);
        FMA2(accA0, kA1, v1.x, accA0);
        FMA2(accA1, kA1, v1.y, accA1);
        FMA2(accA2, kA1, c2.y, accA2);
        FMA2(accB0, kB1, v1.x, accB0);
        FMA2(accB1, kB1, v1.y, accB1);
        FMA2(accB2, kB1, c2.y, accB2);
    }

    float l0, h0, l1, h1, l2, h2;
    unpack2(l0, h0, accA0);
    unpack2(l1, h1, accA1);
    unpack2(l2, h2, accA2);
    out[3 * iA + 0] = scaleA * (l0 + h0);
    out[3 * iA + 1] = scaleA * (l1 + h1);
    out[3 * iA + 2] = scaleA * (l2 + h2);
    if (wB) {
        unpack2(l0, h0, accB0);
        unpack2(l1, h1, accB1);
        unpack2(l2, h2, accB2);
        out[3 * iB + 0] = scaleB * (l0 + h0);
        out[3 * iB + 1] = scaleB * (l1 + h1);
        out[3 * iB + 2] = scaleB * (l2 + h2);
    }
}

extern "C" void kernel_launch(void* const* d_in, const int* in_sizes, int n_in,
                              void* d_out, int out_size)
{
    const float* Points   = (const float*)d_in[0];
    const float* supp_pts = (const float*)d_in[1];
    const float* supp_vec = (const float*)d_in[2];
    const float* Cont     = (const float*)d_in[3];
    float* out = (float*)d_out;

    int N  = in_sizes[0] / 3;       // 65536
    int F  = in_sizes[3];           // 8
    int FM = in_sizes[1] / 3;       // 4096
    int M  = FM / F;                // 512

    size_t smem_bytes = (size_t)FM * 28;  // 7 floats per support point = 114688 B
    cudaFuncSetAttribute(rbf_speed_kernel,
                         cudaFuncAttributeMaxDynamicSharedMemorySize,
                         (int)smem_bytes);

    int pts_per_cta = 2 * BLOCK;
    int grid = (N + pts_per_cta - 1) / pts_per_cta;   // 147 CTAs
    rbf_speed_kernel<<<grid, BLOCK, smem_bytes>>>(
        Points, supp_pts, supp_vec, Cont, out, N, M, FM);
}